// round 16
// baseline (speedup 1.0000x reference)
#include <cuda_runtime.h>
#include <math.h>

// MambaState elementwise update:
//   a      = sigmoid(a_logit)        [D] broadcast over batch
//   delta  = softplus(delta_log)     [D] broadcast over batch
//   new_state = a * prev + delta * (b_t * v_t)
//   y         = c_t * new_state
// Output: [new_state (B*D) | y (B*D)]
//
// B=8192, D=4096, fp32. HBM-bound: 512 MiB read + 256 MiB write.
// Each thread handles float4 elements i and i + N4/2. N4/2 is a multiple
// of D4, so both share the same column -> one param load + one
// sigmoid/softplus pair per two elements, and 8 front-batched streaming
// LDG.128s per thread (MLP_p1~8). Streaming loads/stores use evict-first
// (.cs) hints; params use default caching (L2-resident, 32 KiB total).

#define BATCH     8192
#define STATE_DIM 4096
#define D4        (STATE_DIM / 4)           // 1024 float4 per row
#define N4        ((BATCH * STATE_DIM) / 4) // 8388608 float4 elements
#define HALF4     (N4 / 2)                  // 4194304, multiple of D4

__device__ __forceinline__ float sigmoidf_(float x) {
    return 1.0f / (1.0f + __expf(-x));
}

__device__ __forceinline__ float softplusf_(float x) {
    return fmaxf(x, 0.0f) + log1pf(__expf(-fabsf(x)));
}

__device__ __forceinline__ float4 ldcs4(const float4* p) {
    return __ldcs(p);
}

__global__ __launch_bounds__(256)
void mamba_state_kernel(const float4* __restrict__ prev,
                        const float4* __restrict__ b_t,
                        const float4* __restrict__ v_t,
                        const float4* __restrict__ c_t,
                        const float4* __restrict__ a_logit,
                        const float4* __restrict__ delta_log,
                        float4* __restrict__ out_state,
                        float4* __restrict__ out_y) {
    int i = blockIdx.x * blockDim.x + threadIdx.x;   // float4 index in first half
    int j = i + HALF4;                               // same column (HALF4 % D4 == 0)
    int col = i & (D4 - 1);

    // Front-batch all 8 streaming loads for maximum MLP.
    float4 p0 = ldcs4(prev + i);
    float4 b0 = ldcs4(b_t  + i);
    float4 v0 = ldcs4(v_t  + i);
    float4 c0 = ldcs4(c_t  + i);
    float4 p1 = ldcs4(prev + j);
    float4 b1 = ldcs4(b_t  + j);
    float4 v1 = ldcs4(v_t  + j);
    float4 c1 = ldcs4(c_t  + j);

    // Cached param loads (L2/L1 resident after first wave).
    float4 al = a_logit[col];
    float4 dl = delta_log[col];

    float a0 = sigmoidf_(al.x), a1 = sigmoidf_(al.y),
          a2 = sigmoidf_(al.z), a3 = sigmoidf_(al.w);
    float d0 = softplusf_(dl.x), d1 = softplusf_(dl.y),
          d2 = softplusf_(dl.z), d3 = softplusf_(dl.w);

    float4 ns0, ns1, y0, y1;
    ns0.x = fmaf(a0, p0.x, d0 * (b0.x * v0.x));
    ns0.y = fmaf(a1, p0.y, d1 * (b0.y * v0.y));
    ns0.z = fmaf(a2, p0.z, d2 * (b0.z * v0.z));
    ns0.w = fmaf(a3, p0.w, d3 * (b0.w * v0.w));
    y0.x = c0.x * ns0.x;  y0.y = c0.y * ns0.y;
    y0.z = c0.z * ns0.z;  y0.w = c0.w * ns0.w;

    ns1.x = fmaf(a0, p1.x, d0 * (b1.x * v1.x));
    ns1.y = fmaf(a1, p1.y, d1 * (b1.y * v1.y));
    ns1.z = fmaf(a2, p1.z, d2 * (b1.z * v1.z));
    ns1.w = fmaf(a3, p1.w, d3 * (b1.w * v1.w));
    y1.x = c1.x * ns1.x;  y1.y = c1.y * ns1.y;
    y1.z = c1.z * ns1.z;  y1.w = c1.w * ns1.w;

    __stcs(out_state + i, ns0);
    __stcs(out_y     + i, y0);
    __stcs(out_state + j, ns1);
    __stcs(out_y     + j, y1);
}

extern "C" void kernel_launch(void* const* d_in, const int* in_sizes, int n_in,
                              void* d_out, int out_size) {
    const float4* prev      = (const float4*)d_in[0];
    const float4* b_t       = (const float4*)d_in[1];
    const float4* v_t       = (const float4*)d_in[2];
    const float4* c_t       = (const float4*)d_in[3];
    const float4* a_logit   = (const float4*)d_in[4];
    const float4* delta_log = (const float4*)d_in[5];

    float* out = (float*)d_out;
    float4* out_state = (float4*)out;                         // first B*D floats
    float4* out_y     = (float4*)(out + BATCH * STATE_DIM);   // second B*D floats

    const int threads = 256;
    const int blocks  = HALF4 / threads;                      // 16384, exact
    mamba_state_kernel<<<blocks, threads>>>(prev, b_t, v_t, c_t,
                                            a_logit, delta_log,
                                            out_state, out_y);
}